// round 6
// baseline (speedup 1.0000x reference)
#include <cuda_runtime.h>

// x:   [B=2, 1, D=64, H=256, W=256] fp32
// out: [B=2, 16, D=64, H=256, W=256] fp32
//   even channel -> per-slice 2D sobel magnitude, odd channel -> x
//
// Warp = one full 256-px row. Lane owns 8 contiguous px (32B).
// Blackwell 256-bit vector ld/st: 3 x LDG.256 + 16 x STG.256 per thread.
// Each warp store = 1KB contiguous (perfect coalescing). Halos via 6 shuffles.

#define W 256
#define H 256
#define DD 64
#define NB 2

#define LDG256(r, p)                                                        \
    asm volatile("ld.global.nc.v8.f32 {%0,%1,%2,%3,%4,%5,%6,%7}, [%8];"    \
        : "=f"((r)[0]), "=f"((r)[1]), "=f"((r)[2]), "=f"((r)[3]),           \
          "=f"((r)[4]), "=f"((r)[5]), "=f"((r)[6]), "=f"((r)[7])            \
        : "l"(p))

#define STG256(p, r)                                                        \
    asm volatile("st.global.cs.v8.f32 [%0], {%1,%2,%3,%4,%5,%6,%7,%8};"    \
        :: "l"(p),                                                          \
           "f"((r)[0]), "f"((r)[1]), "f"((r)[2]), "f"((r)[3]),              \
           "f"((r)[4]), "f"((r)[5]), "f"((r)[6]), "f"((r)[7])               \
        : "memory")

__device__ __forceinline__ float fsqrt_approx(float a) {
    float r;
    asm("sqrt.approx.f32 %0, %1;" : "=f"(r) : "f"(a));
    return r;
}

__global__ __launch_bounds__(256) void sobel_cat_kernel(
    const float* __restrict__ x, float* __restrict__ out)
{
    const int warp = blockIdx.x * (blockDim.x >> 5) + (threadIdx.x >> 5);
    const int lane = threadIdx.x & 31;
    const int h    = warp & (H - 1);
    const int bd   = warp >> 8;          // b*D + d
    const int w0   = lane << 3;          // 8 px per lane

    const float* base = x + ((size_t)bd * H + h) * W + w0;

    float t[8], m[8], b[8];
    LDG256(m, base);
    if (h > 0) {
        LDG256(t, base - W);
    } else {
#pragma unroll
        for (int i = 0; i < 8; i++) t[i] = 0.f;
    }
    if (h < H - 1) {
        LDG256(b, base + W);
    } else {
#pragma unroll
        for (int i = 0; i < 8; i++) b[i] = 0.f;
    }

    // halos: warp owns the whole row -> only neighbor-lane shuffles needed
    const unsigned full = 0xFFFFFFFFu;
    float tl = __shfl_up_sync(full, t[7], 1);
    float ml = __shfl_up_sync(full, m[7], 1);
    float bl = __shfl_up_sync(full, b[7], 1);
    float tr = __shfl_down_sync(full, t[0], 1);
    float mr = __shfl_down_sync(full, m[0], 1);
    float br = __shfl_down_sync(full, b[0], 1);
    if (lane == 0)  { tl = 0.f; ml = 0.f; bl = 0.f; }
    if (lane == 31) { tr = 0.f; mr = 0.f; br = 0.f; }

    float T[10], M[10], Bt[10];
    T[0] = tl;  M[0] = ml;  Bt[0] = bl;
#pragma unroll
    for (int i = 0; i < 8; i++) { T[i+1] = t[i]; M[i+1] = m[i]; Bt[i+1] = b[i]; }
    T[9] = tr;  M[9] = mr;  Bt[9] = br;

    float s[8];
#pragma unroll
    for (int i = 0; i < 8; i++) {
        float gx = (T[i+2] - T[i]) + 2.f*(M[i+2] - M[i]) + (Bt[i+2] - Bt[i]);
        float gy = (Bt[i] - T[i]) + 2.f*(Bt[i+1] - T[i+1]) + (Bt[i+2] - T[i+2]);
        s[i] = fsqrt_approx(gx*gx + gy*gy);
    }

    const int bb = bd >> 6;           // bd / D
    const int dd = bd & (DD - 1);     // bd % D
    const size_t cs = (size_t)DD * H * W;   // channel stride (elems)
    float* obase = out + (((size_t)bb * 16 * DD + dd) * H + h) * W + w0;

#pragma unroll
    for (int c = 0; c < 8; c++) {
        float* p = obase + (size_t)(2 * c) * cs;   // sobel channel
        STG256(p, s);
        STG256(p + cs, m);                         // copy channel
    }
}

extern "C" void kernel_launch(void* const* d_in, const int* in_sizes, int n_in,
                              void* d_out, int out_size)
{
    const float* x = (const float*)d_in[0];
    float* out = (float*)d_out;

    // one warp per row: NB*DD*H = 32768 warps, 8 warps/block
    const int total_warps = NB * DD * H;
    const int threads = 256;
    const int blocks = total_warps * 32 / threads;   // 4096
    sobel_cat_kernel<<<blocks, threads>>>(x, out);
}